// round 4
// baseline (speedup 1.0000x reference)
#include <cuda_runtime.h>
#include <cstdint>

#define ROWS 65536
#define H 256
#define IN_SHAPE 512
#define NA 32
#define NACT 16
#define G3 768   // 3*H

// ---------------- scratch (allocation-free: __device__ globals) -------------
__device__ float g_x [(size_t)ROWS * H];
__device__ float g_gi[(size_t)ROWS * G3];
__device__ float g_h0[(size_t)ROWS * H];
__device__ float g_h1[(size_t)ROWS * H];
__device__ float g_c [(size_t)ROWS * H];
__device__ float g_nb[(size_t)ROWS * NA];
__device__ float g_invn[(size_t)ROWS];

__device__ __forceinline__ uint32_t f2tf32(float v) {
    uint32_t u;
    asm("cvt.rna.tf32.f32 %0, %1;" : "=r"(u) : "f"(v));
    return u;
}
__device__ __forceinline__ float sigm(float x) { return 1.0f / (1.0f + __expf(-x)); }
__device__ __forceinline__ float tanh_fast(float x) {
    return 2.0f / (1.0f + __expf(-2.0f * x)) - 1.0f;
}

#define MMA_TF32_16x8(d, a0, a1, a2, a3, b0, b1) \
    asm volatile( \
        "mma.sync.aligned.m16n8k8.row.col.f32.tf32.tf32.f32 " \
        "{%0,%1,%2,%3}, {%4,%5,%6,%7}, {%8,%9}, {%0,%1,%2,%3};" \
        : "+f"((d)[0]), "+f"((d)[1]), "+f"((d)[2]), "+f"((d)[3]) \
        : "r"(a0), "r"(a1), "r"(a2), "r"(a3), "r"(b0), "r"(b1))

// ---------------- tf32 mma.sync GEMM ----------------------------------------
// C[m,n] = sum_k A[m,k]*B[n,k] + bias[n]   (A: MxK, B: NxK, row-major fp32)
// BM=128, BN=128, BK=32; 8 warps as 2(M) x 4(N); warp tile 64x32.
template <int RELU>
__global__ __launch_bounds__(256) void gemm_mma(
    const float* __restrict__ A, const float* __restrict__ B,
    const float* __restrict__ bias, float* __restrict__ C,
    int M, int N, int K)
{
    __shared__ uint32_t As[128][36];
    __shared__ uint32_t Bs[128][36];

    const int tid = threadIdx.x;
    const int wid = tid >> 5;
    const int lane = tid & 31;
    const int gr = lane >> 2;
    const int tg = lane & 3;

    const int bm = blockIdx.y * 128;
    const int bn = blockIdx.x * 128;
    const int wm = (wid & 1) * 64;
    const int wn = (wid >> 1) * 32;

    const int lr = tid >> 3;
    const int lf = tid & 7;

    const float* Ap = A + (long)(bm + lr) * K + lf * 4;
    const float* Bp = B + (long)(bn + lr) * K + lf * 4;
    const long strideA = (long)32 * K;

    float acc[4][4][4];
#pragma unroll
    for (int i = 0; i < 4; i++)
#pragma unroll
        for (int j = 0; j < 4; j++)
#pragma unroll
            for (int e = 0; e < 4; e++) acc[i][j][e] = 0.0f;

    float4 ar[4], br[4];
#pragma unroll
    for (int i = 0; i < 4; i++) {
        ar[i] = *(const float4*)(Ap + i * strideA);
        br[i] = *(const float4*)(Bp + i * strideA);
    }

    for (int k0 = 0; k0 < K; k0 += 32) {
        __syncthreads();
#pragma unroll
        for (int i = 0; i < 4; i++) {
            const int r = lr + i * 32;
            As[r][lf * 4 + 0] = f2tf32(ar[i].x);
            As[r][lf * 4 + 1] = f2tf32(ar[i].y);
            As[r][lf * 4 + 2] = f2tf32(ar[i].z);
            As[r][lf * 4 + 3] = f2tf32(ar[i].w);
            Bs[r][lf * 4 + 0] = f2tf32(br[i].x);
            Bs[r][lf * 4 + 1] = f2tf32(br[i].y);
            Bs[r][lf * 4 + 2] = f2tf32(br[i].z);
            Bs[r][lf * 4 + 3] = f2tf32(br[i].w);
        }
        __syncthreads();

        if (k0 + 32 < K) {
#pragma unroll
            for (int i = 0; i < 4; i++) {
                ar[i] = *(const float4*)(Ap + (k0 + 32) + i * strideA);
                br[i] = *(const float4*)(Bp + (k0 + 32) + i * strideA);
            }
        }

#pragma unroll
        for (int kk = 0; kk < 4; kk++) {
            const int kb = kk * 8;
            uint32_t af[4][4];
            uint32_t bf[4][2];
#pragma unroll
            for (int i = 0; i < 4; i++) {
                const int r0 = wm + 16 * i + gr;
                af[i][0] = As[r0][kb + tg];
                af[i][1] = As[r0 + 8][kb + tg];
                af[i][2] = As[r0][kb + tg + 4];
                af[i][3] = As[r0 + 8][kb + tg + 4];
            }
#pragma unroll
            for (int j = 0; j < 4; j++) {
                const int n0 = wn + 8 * j + gr;
                bf[j][0] = Bs[n0][kb + tg];
                bf[j][1] = Bs[n0][kb + tg + 4];
            }
#pragma unroll
            for (int i = 0; i < 4; i++)
#pragma unroll
                for (int j = 0; j < 4; j++)
                    MMA_TF32_16x8(acc[i][j], af[i][0], af[i][1], af[i][2], af[i][3],
                                  bf[j][0], bf[j][1]);
        }
    }

#pragma unroll
    for (int j = 0; j < 4; j++) {
        const int col = bn + wn + 8 * j + 2 * tg;
        const float2 bb = *(const float2*)&bias[col];
#pragma unroll
        for (int i = 0; i < 4; i++) {
            const long r0 = (long)(bm + wm + 16 * i + gr);
            float2 v0, v1;
            v0.x = acc[i][j][0] + bb.x;
            v0.y = acc[i][j][1] + bb.y;
            v1.x = acc[i][j][2] + bb.x;
            v1.y = acc[i][j][3] + bb.y;
            if (RELU) {
                v0.x = fmaxf(v0.x, 0.0f); v0.y = fmaxf(v0.y, 0.0f);
                v1.x = fmaxf(v1.x, 0.0f); v1.y = fmaxf(v1.y, 0.0f);
            }
            *(float2*)&C[r0 * N + col] = v0;
            *(float2*)&C[(r0 + 8) * N + col] = v1;
        }
    }
}

// ---------------- fused state-side GEMM + GRU gates --------------------------
// Computes gh = A @ W^T (+bhh) for three gate blocks {c, c+256, c+512} of a
// 128-wide H-column tile, then applies GRU gates with gi (precomputed) and
// blend source A, writing h directly. A: [ROWS][256], W: [768][256].
// BM=64, BNH=128, BK=32; 8 warps as 1x8 over N; warp tile 64x16 per gate.
__global__ __launch_bounds__(256) void gemm_gru(
    const float* __restrict__ A, const float* __restrict__ W,
    const float* __restrict__ bhh, const float* __restrict__ gi,
    float* __restrict__ out0, float* __restrict__ out1)
{
    __shared__ uint32_t As[64][36];
    __shared__ uint32_t Bs[384][36];
    __shared__ float bS[384];

    const int tid = threadIdx.x;
    const int wid = tid >> 5;
    const int lane = tid & 31;
    const int gr = lane >> 2;
    const int tg = lane & 3;

    const int bn = blockIdx.x * 128;   // H-column tile (0 or 128)
    const int bm = blockIdx.y * 64;    // row tile
    const int wn = wid * 16;

    for (int t = tid; t < 384; t += 256)
        bS[t] = bhh[(t >> 7) * 256 + bn + (t & 127)];

    // global load mapping (f4 granularity, 8 f4 per 32-k row-chunk)
    // A: 64 rows -> 512 f4, 2 per thread; B: 384 rows -> 3072 f4, 12 per thread
    const int raA[2] = { tid >> 3, (tid + 256) >> 3 };
    const int faA[2] = { tid & 7, (tid + 256) & 7 };

    float acc[3][4][2][4];
#pragma unroll
    for (int g = 0; g < 3; g++)
#pragma unroll
        for (int i = 0; i < 4; i++)
#pragma unroll
            for (int j = 0; j < 2; j++)
#pragma unroll
                for (int e = 0; e < 4; e++) acc[g][i][j][e] = 0.0f;

    float4 pa[2], pb[12];
#pragma unroll
    for (int u = 0; u < 2; u++)
        pa[u] = *(const float4*)(A + (long)(bm + raA[u]) * 256 + faA[u] * 4);
#pragma unroll
    for (int u = 0; u < 12; u++) {
        const int idx = u * 256 + tid;
        const int r = idx >> 3, f = idx & 7;
        const int wr = bn + (r & 127) + (r >> 7) * 256;
        pb[u] = *(const float4*)(W + (long)wr * 256 + f * 4);
    }

    for (int k0 = 0; k0 < 256; k0 += 32) {
        __syncthreads();
#pragma unroll
        for (int u = 0; u < 2; u++) {
            As[raA[u]][faA[u] * 4 + 0] = f2tf32(pa[u].x);
            As[raA[u]][faA[u] * 4 + 1] = f2tf32(pa[u].y);
            As[raA[u]][faA[u] * 4 + 2] = f2tf32(pa[u].z);
            As[raA[u]][faA[u] * 4 + 3] = f2tf32(pa[u].w);
        }
#pragma unroll
        for (int u = 0; u < 12; u++) {
            const int idx = u * 256 + tid;
            const int r = idx >> 3, f = idx & 7;
            Bs[r][f * 4 + 0] = f2tf32(pb[u].x);
            Bs[r][f * 4 + 1] = f2tf32(pb[u].y);
            Bs[r][f * 4 + 2] = f2tf32(pb[u].z);
            Bs[r][f * 4 + 3] = f2tf32(pb[u].w);
        }
        __syncthreads();

        if (k0 + 32 < 256) {
            const int kn = k0 + 32;
#pragma unroll
            for (int u = 0; u < 2; u++)
                pa[u] = *(const float4*)(A + (long)(bm + raA[u]) * 256 + kn + faA[u] * 4);
#pragma unroll
            for (int u = 0; u < 12; u++) {
                const int idx = u * 256 + tid;
                const int r = idx >> 3, f = idx & 7;
                const int wr = bn + (r & 127) + (r >> 7) * 256;
                pb[u] = *(const float4*)(W + (long)wr * 256 + kn + f * 4);
            }
        }

#pragma unroll
        for (int kk = 0; kk < 4; kk++) {
            const int kb = kk * 8;
            uint32_t af[4][4];
#pragma unroll
            for (int i = 0; i < 4; i++) {
                const int r0 = 16 * i + gr;
                af[i][0] = As[r0][kb + tg];
                af[i][1] = As[r0 + 8][kb + tg];
                af[i][2] = As[r0][kb + tg + 4];
                af[i][3] = As[r0 + 8][kb + tg + 4];
            }
#pragma unroll
            for (int g = 0; g < 3; g++)
#pragma unroll
                for (int j = 0; j < 2; j++) {
                    const int n0 = g * 128 + wn + 8 * j + gr;
                    const uint32_t b0 = Bs[n0][kb + tg];
                    const uint32_t b1 = Bs[n0][kb + tg + 4];
#pragma unroll
                    for (int i = 0; i < 4; i++)
                        MMA_TF32_16x8(acc[g][i][j], af[i][0], af[i][1], af[i][2],
                                      af[i][3], b0, b1);
                }
        }
    }

    // epilogue: gates
#pragma unroll
    for (int j = 0; j < 2; j++) {
        const int cl = wn + 8 * j + 2 * tg;      // col within 128-tile
        const int col = bn + cl;                 // global H col
        const float2 bR = *(const float2*)&bS[cl];
        const float2 bZ = *(const float2*)&bS[128 + cl];
        const float2 bN = *(const float2*)&bS[256 + cl];
#pragma unroll
        for (int i = 0; i < 4; i++) {
#pragma unroll
            for (int half = 0; half < 2; half++) {
                const long row = (long)(bm + 16 * i + gr + 8 * half);
                const int e = 2 * half;          // acc elements e, e+1
                const float2 giR = *(const float2*)&gi[row * G3 + col];
                const float2 giZ = *(const float2*)&gi[row * G3 + col + 256];
                const float2 giN = *(const float2*)&gi[row * G3 + col + 512];
                const float2 av = *(const float2*)&A[row * 256 + col];
                float2 o;
                {
                    const float r = sigm(giR.x + acc[0][i][j][e] + bR.x);
                    const float z = sigm(giZ.x + acc[1][i][j][e] + bZ.x);
                    const float n = tanh_fast(giN.x + r * (acc[2][i][j][e] + bN.x));
                    o.x = (1.0f - z) * n + z * av.x;
                }
                {
                    const float r = sigm(giR.y + acc[0][i][j][e + 1] + bR.y);
                    const float z = sigm(giZ.y + acc[1][i][j][e + 1] + bZ.y);
                    const float n = tanh_fast(giN.y + r * (acc[2][i][j][e + 1] + bN.y));
                    o.y = (1.0f - z) * n + z * av.y;
                }
                *(float2*)&out0[row * 256 + col] = o;
                if (out1) *(float2*)&out1[row * 256 + col] = o;
            }
        }
    }
}

// ---------------- neighbor extraction ----------------------------------------
__global__ __launch_bounds__(256) void nb_kernel(
    const float* __restrict__ inp, float* __restrict__ nb, float* __restrict__ invn)
{
    int idx = blockIdx.x * 256 + threadIdx.x;
    int row = idx >> 5;
    int j = idx & 31;
    int i = row & 31;
    float v = 0.0f;
    if (j != i) {
        int k = (j > i) ? (j - 1) : j;
        v = inp[(long)row * IN_SHAPE + 260 + 8 * k];
    }
    float s = v;
#pragma unroll
    for (int o = 16; o > 0; o >>= 1) s += __shfl_xor_sync(0xffffffffu, s, o);
    nb[idx] = v;
    if (j == 0) invn[row] = 1.0f / s;
}

// ---------------- comm mix ---------------------------------------------------
__global__ __launch_bounds__(256) void comm_mix(
    const float* __restrict__ h, const float* __restrict__ nb,
    const float* __restrict__ invn, float* __restrict__ out)
{
    __shared__ float hs[32][256];
    __shared__ float At[32][36];
    __shared__ float sinv[32];

    int b = blockIdx.x;
    int tid = threadIdx.x;
    const float* hb = h + (long)b * 32 * 256;

#pragma unroll
    for (int t = tid; t < 2048; t += 256) {
        int r = t >> 6;
        int c4 = (t & 63) << 2;
        *(float4*)&hs[r][c4] = *(const float4*)&hb[r * 256 + c4];
    }
#pragma unroll
    for (int t = tid; t < 1024; t += 256) {
        int i = t >> 5;
        int j = t & 31;
        At[j][i] = nb[(long)(b * 32 + i) * 32 + j];
    }
    if (tid < 32) sinv[tid] = invn[b * 32 + tid];
    __syncthreads();

    float acc[32];
#pragma unroll
    for (int i = 0; i < 32; i++) acc[i] = 0.0f;

#pragma unroll 4
    for (int j = 0; j < 32; j++) {
        float hv = hs[j][tid];
#pragma unroll
        for (int i4 = 0; i4 < 32; i4 += 4) {
            float4 a = *(const float4*)&At[j][i4];
            acc[i4 + 0] += a.x * hv;
            acc[i4 + 1] += a.y * hv;
            acc[i4 + 2] += a.z * hv;
            acc[i4 + 3] += a.w * hv;
        }
    }
#pragma unroll
    for (int i = 0; i < 32; i++)
        out[(long)(b * 32 + i) * 256 + tid] = acc[i] * sinv[i];
}

// ---------------- q projection -----------------------------------------------
__global__ __launch_bounds__(256) void qproj(
    const float* __restrict__ h, const float* __restrict__ W2,
    const float* __restrict__ b2, float* __restrict__ q)
{
    __shared__ float ws[16][260];
    __shared__ float hsm[16][256];
    int tid = threadIdx.x;

#pragma unroll
    for (int t = tid; t < 1024; t += 256) {
        int n = t >> 6;
        int k4 = (t & 63) << 2;
        *(float4*)&ws[n][k4] = *(const float4*)&W2[n * 256 + k4];
    }
    const float* hb = h + (long)blockIdx.x * 16 * 256;
#pragma unroll
    for (int t = tid; t < 1024; t += 256) {
        int r = t >> 6;
        int k4 = (t & 63) << 2;
        *(float4*)&hsm[r][k4] = *(const float4*)&hb[r * 256 + k4];
    }
    __syncthreads();

    int r = tid >> 4;
    int n = tid & 15;
    float s = 0.0f;
#pragma unroll 8
    for (int k = 0; k < 256; k += 4) {
        float4 hv = *(const float4*)&hsm[r][k];
        float4 wv = *(const float4*)&ws[n][k];
        s += hv.x * wv.x + hv.y * wv.y + hv.z * wv.z + hv.w * wv.w;
    }
    q[(long)(blockIdx.x * 16 + r) * 16 + n] = s + b2[n];
}

// ---------------- orchestration ----------------------------------------------
extern "C" void kernel_launch(void* const* d_in, const int* in_sizes, int n_in,
                              void* d_out, int out_size)
{
    (void)in_sizes; (void)n_in; (void)out_size;
    const float* inputs = (const float*)d_in[0];
    const float* hidden = (const float*)d_in[1];
    const float* W1     = (const float*)d_in[2];
    const float* b1     = (const float*)d_in[3];
    const float* rWih   = (const float*)d_in[4];
    const float* rWhh   = (const float*)d_in[5];
    const float* rbih   = (const float*)d_in[6];
    const float* rbhh   = (const float*)d_in[7];
    const float* cWih   = (const float*)d_in[8];
    const float* cWhh   = (const float*)d_in[9];
    const float* cbih   = (const float*)d_in[10];
    const float* cbhh   = (const float*)d_in[11];
    const float* W2     = (const float*)d_in[12];
    const float* b2     = (const float*)d_in[13];

    float* q_out = (float*)d_out;
    float* hrnn_out = q_out + (long)ROWS * NACT;

    float *x, *gi, *h0, *h1, *c, *nb, *invn;
    cudaGetSymbolAddress((void**)&x, g_x);
    cudaGetSymbolAddress((void**)&gi, g_gi);
    cudaGetSymbolAddress((void**)&h0, g_h0);
    cudaGetSymbolAddress((void**)&h1, g_h1);
    cudaGetSymbolAddress((void**)&c, g_c);
    cudaGetSymbolAddress((void**)&nb, g_nb);
    cudaGetSymbolAddress((void**)&invn, g_invn);

    dim3 blk(256);
    dim3 gridGru(2, ROWS / 64);

    nb_kernel<<<ROWS * 32 / 256, blk>>>(inputs, nb, invn);

    // x = relu(inputs @ W1^T + b1)
    gemm_mma<1><<<dim3(H / 128, ROWS / 128), blk>>>(inputs, W1, b1, x, ROWS, H, IN_SHAPE);

    // h_rnn = GRU(x, hidden): gi = x @ rWih^T + rbih; fused gh+gates
    gemm_mma<0><<<dim3(G3 / 128, ROWS / 128), blk>>>(x, rWih, rbih, gi, ROWS, G3, H);
    gemm_gru<<<gridGru, blk>>>(hidden, rWhh, rbhh, gi, h0, hrnn_out);

    float* hc = h0;
    float* hn = h1;
    for (int s = 0; s < 4; s++) {
        comm_mix<<<ROWS / NA, blk>>>(hc, nb, invn, c);
        gemm_mma<0><<<dim3(G3 / 128, ROWS / 128), blk>>>(hc, cWih, cbih, gi, ROWS, G3, H);
        gemm_gru<<<gridGru, blk>>>(c, cWhh, cbhh, gi, hn, nullptr);
        float* t2 = hc; hc = hn; hn = t2;
    }

    qproj<<<ROWS / 16, blk>>>(hc, W2, b2, q_out);
}